// round 8
// baseline (speedup 1.0000x reference)
#include <cuda_runtime.h>
#include <cstdint>

// FPS B=16, N=65536, S=2048, out = coords of selected (B,S,3) f32.
// Cluster of 8 CTAs/batch, 512 thr/CTA. Per-thread 16 points held REGISTER-
// RESIDENT as negated packed f32x2 pairs (coords never change) -> no LDS in
// the hot loop. Packed add/mul.rn.f32x2 distance math (per-lane IEEE RN,
// bit-identical to scalar). Value-only max (redux.sync) + parallel-min
// equality rescan for exact first-index argmax; split-u32 redux CTA reduce;
// DSMEM push + mbarrier cluster exchange (winner coords ride with the key).

#define NBATCH   16
#define NPTS     65536
#define NSAMP    2048
#define CLUSTER  8
#define NPC      (NPTS / CLUSTER)     // 8192
#define THREADS  512
#define NWARPS   (THREADS / 32)       // 16
#define PPT      (NPC / THREADS)      // 16
#define PAIRS    (PPT / 2)            // 8 packed pairs per thread

typedef unsigned long long u64;

// 32-byte slot: key @0 (8-aligned), xy packed @8 (8-aligned), z @16.
struct __align__(16) Slot { u64 key; u64 xy; float z; float pad[3]; };

struct __align__(16) Smem {
    float x[NPC];                // negated coords (for winner lookup only)
    float y[NPC];
    float z[NPC];
    u64   wkey[NWARPS];          // per-warp packed (valBits<<32)|~localIdx
    Slot  slots[2][CLUSTER];     // parity-double-buffered cluster exchange
    u64   mbar;
};

__device__ __forceinline__ uint32_t smem_u32(const void* p) {
    return (uint32_t)__cvta_generic_to_shared(p);
}
__device__ __forceinline__ u64 pk2(float lo, float hi) {
    u64 r; asm("mov.b64 %0, {%1, %2};" : "=l"(r) : "f"(lo), "f"(hi)); return r;
}
__device__ __forceinline__ void upk2(float& lo, float& hi, u64 v) {
    asm("mov.b64 {%0, %1}, %2;" : "=f"(lo), "=f"(hi) : "l"(v));
}
__device__ __forceinline__ u64 add2(u64 a, u64 b) {
    u64 r; asm("add.rn.f32x2 %0, %1, %2;" : "=l"(r) : "l"(a), "l"(b)); return r;
}
__device__ __forceinline__ u64 mul2(u64 a, u64 b) {
    u64 r; asm("mul.rn.f32x2 %0, %1, %2;" : "=l"(r) : "l"(a), "l"(b)); return r;
}
__device__ __forceinline__ unsigned redux_max(unsigned v) {
    unsigned r; asm("redux.sync.max.u32 %0, %1, 0xffffffff;" : "=r"(r) : "r"(v)); return r;
}
__device__ __forceinline__ unsigned redux_min(unsigned v) {
    unsigned r; asm("redux.sync.min.u32 %0, %1, 0xffffffff;" : "=r"(r) : "r"(v)); return r;
}

__global__ void __launch_bounds__(THREADS, 1)
fps_kernel(const float* __restrict__ pc, float* __restrict__ out)
{
    extern __shared__ char smraw[];
    Smem& s = *reinterpret_cast<Smem*>(smraw);

    const int tid  = threadIdx.x;
    const int lane = tid & 31;
    const int warp = tid >> 5;
    const int rank = blockIdx.x & (CLUSTER - 1);
    const int b    = blockIdx.x >> 3;

    const float* __restrict__ base = pc + (size_t)b * NPTS * 3;

    // ---- prologue: stage NEGATED coords as SoA (winner lookup table) ----
    for (int i = tid; i < NPC; i += THREADS) {
        int gi = rank * NPC + i;
        s.x[i] = -base[gi * 3 + 0];
        s.y[i] = -base[gi * 3 + 1];
        s.z[i] = -base[gi * 3 + 2];
    }
    if (tid == 0) {
        asm volatile("mbarrier.init.shared.b64 [%0], %1;"
                     :: "r"(smem_u32(&s.mbar)), "r"(CLUSTER) : "memory");
    }
    __syncthreads();

    // ---- load this thread's 16 points into registers as packed pairs ----
    u64 px[PAIRS], py[PAIRS], pz[PAIRS];
    #pragma unroll
    for (int g = 0; g < 4; ++g) {
        const int bi = g * (THREADS * 4) + tid * 4;
        ulonglong2 X = *reinterpret_cast<const ulonglong2*>(&s.x[bi]);
        ulonglong2 Y = *reinterpret_cast<const ulonglong2*>(&s.y[bi]);
        ulonglong2 Z = *reinterpret_cast<const ulonglong2*>(&s.z[bi]);
        px[g*2+0] = X.x; px[g*2+1] = X.y;
        py[g*2+0] = Y.x; py[g*2+1] = Y.y;
        pz[g*2+0] = Z.x; pz[g*2+1] = Z.y;
    }

    float closest[PPT];
    #pragma unroll
    for (int i = 0; i < PPT; i++) closest[i] = __int_as_float(0x7f800000);

    float sx = base[0], sy = base[1], sz = base[2];   // initial selection: point 0

    asm volatile("barrier.cluster.arrive.aligned;" ::: "memory");
    asm volatile("barrier.cluster.wait.aligned;"   ::: "memory");

    const uint32_t mb_addr = smem_u32(&s.mbar);

    for (int it = 0; it < NSAMP; ++it) {
        const int p = it & 1;

        u64 sxx = pk2(sx, sx), syy = pk2(sy, sy), szz = pk2(sz, sz);

        // ---- distance update + running min; value-only max (pure reg FP) ----
        float vmax = 0.0f;
        #pragma unroll
        for (int q = 0; q < PAIRS; ++q) {
            // d = (s + (-x))^2 + (s + (-y))^2 + (s + (-z))^2, per-lane IEEE RN
            u64 dx = add2(sxx, px[q]);
            u64 dy = add2(syy, py[q]);
            u64 dz = add2(szz, pz[q]);
            u64 d  = add2(add2(mul2(dx, dx), mul2(dy, dy)), mul2(dz, dz));
            float d0, d1; upk2(d0, d1, d);
            float c0 = fminf(closest[q*2+0], d0); closest[q*2+0] = c0;
            float c1 = fminf(closest[q*2+1], d1); closest[q*2+1] = c1;
            vmax = fmaxf(vmax, c0); vmax = fmaxf(vmax, c1);
        }

        // ---- warp reduce: redux max on float bits (all >= 0) ----
        const unsigned wmax = redux_max(__float_as_uint(vmax));

        // exact first index: parallel min over matching indices
        // pair q holds points (q>>1)*2048 + tid*4 + (q&1)*2 + {0,1}
        unsigned my = 0xffffffffu;
        #pragma unroll
        for (int q = 0; q < PAIRS; ++q) {
            #pragma unroll
            for (int j = 0; j < 2; ++j) {
                unsigned cand = (unsigned)((q >> 1) * (THREADS * 4) + tid * 4 + (q & 1) * 2 + j);
                if (__float_as_uint(closest[q*2+j]) == wmax)
                    my = (cand < my) ? cand : my;
            }
        }
        const unsigned wmin = redux_min(my);
        if (lane == 0)
            s.wkey[warp] = ((u64)wmax << 32) | (u64)(unsigned)(~wmin);
        __syncthreads();

        // ---- CTA reduce (warp 0, split-u32 redux) + push to all 8 peers ----
        if (warp == 0) {
            u64 wk = (lane < NWARPS) ? s.wkey[lane] : 0ull;
            unsigned vhi = (unsigned)(wk >> 32);
            unsigned vlo = (unsigned)wk;                 // ~localIdx
            unsigned Vmax = redux_max(vhi);
            unsigned nli  = redux_max((vhi == Vmax) ? vlo : 0u);  // max ~idx = min idx
            if (lane < CLUSTER) {
                unsigned li   = ~nli;
                unsigned gidx = (unsigned)rank * NPC + li;
                u64 ckey = ((u64)Vmax << 32) | (u64)(unsigned)(~gidx);
                float cx = -s.x[li], cy = -s.y[li], cz = -s.z[li];   // un-negate
                u64 xy = pk2(cx, cy);
                uint32_t sl = smem_u32(&s.slots[p][rank]);
                uint32_t rs, rb;
                asm volatile("mapa.shared::cluster.u32 %0, %1, %2;" : "=r"(rs) : "r"(sl),      "r"(lane));
                asm volatile("mapa.shared::cluster.u32 %0, %1, %2;" : "=r"(rb) : "r"(mb_addr), "r"(lane));
                asm volatile("st.shared::cluster.b64 [%0],    %1;" :: "r"(rs), "l"(ckey) : "memory");
                asm volatile("st.shared::cluster.b64 [%0+8],  %1;" :: "r"(rs), "l"(xy)   : "memory");
                asm volatile("st.shared::cluster.f32 [%0+16], %1;" :: "r"(rs), "f"(cz)   : "memory");
                asm volatile("mbarrier.arrive.release.cluster.shared::cluster.b64 _, [%0];"
                             :: "r"(rb) : "memory");
            }
        }

        // ---- wait for all 8 publishes ----
        asm volatile(
            "{\n\t.reg .pred P;\n"
            "W%=:\n\t"
            "mbarrier.try_wait.parity.acquire.cluster.shared::cta.b64 P, [%0], %1, 0x989680;\n\t"
            "@P bra.uni D%=;\n\t"
            "bra.uni W%=;\n"
            "D%=:\n\t}"
            :: "r"(mb_addr), "r"(p) : "memory");

        // ---- scan 8 local slots; winner coords are local ----
        const Slot* sl = s.slots[p];
        u64 bk = sl[0].key;
        int br = 0;
        #pragma unroll
        for (int r = 1; r < CLUSTER; ++r) {
            u64 kr = sl[r].key;
            if (kr > bk) { bk = kr; br = r; }
        }
        float nsx, nsy;
        upk2(nsx, nsy, sl[br].xy);
        float nsz = sl[br].z;

        if (rank == 0 && tid == 0) {
            float* o = out + ((size_t)b * NSAMP + it) * 3;
            o[0] = nsx; o[1] = nsy; o[2] = nsz;
        }
        sx = nsx; sy = nsy; sz = nsz;
    }
}

extern "C" void kernel_launch(void* const* d_in, const int* in_sizes, int n_in,
                              void* d_out, int out_size)
{
    (void)in_sizes; (void)n_in; (void)out_size;
    const float* pc  = (const float*)d_in[0];
    float*       out = (float*)d_out;

    static bool attr_set = false;
    if (!attr_set) {
        cudaFuncSetAttribute(fps_kernel,
                             cudaFuncAttributeMaxDynamicSharedMemorySize,
                             (int)sizeof(Smem));
        attr_set = true;
    }

    cudaLaunchConfig_t cfg = {};
    cfg.gridDim = dim3(NBATCH * CLUSTER, 1, 1);
    cfg.blockDim = dim3(THREADS, 1, 1);
    cfg.dynamicSmemBytes = sizeof(Smem);
    cfg.stream = 0;
    cudaLaunchAttribute attrs[1];
    attrs[0].id = cudaLaunchAttributeClusterDimension;
    attrs[0].val.clusterDim = {CLUSTER, 1, 1};
    cfg.attrs = attrs;
    cfg.numAttrs = 1;
    cudaLaunchKernelEx(&cfg, fps_kernel, pc, out);
}

// round 9
// speedup vs baseline: 2.1206x; 2.1206x over previous
#include <cuda_runtime.h>
#include <cstdint>

// FPS B=16, N=65536, S=2048, out = coords of selected (B,S,3) f32.
// R7 base (proven 3702us): cluster 8 CTAs/batch, 512 thr/CTA, NEGATED coords
// SoA in smem loaded as ulonglong2 feeding packed add/mul.rn.f32x2 (per-lane
// IEEE RN, bit-identical). Value-only max (redux.sync) + parallel-min rescan
// for exact first-index argmax.
// R9 edits: split-u32 redux CTA reduce (validated in R8); v2.b64 compact
// DSMEM push.

#define NBATCH   16
#define NPTS     65536
#define NSAMP    2048
#define CLUSTER  8
#define NPC      (NPTS / CLUSTER)     // 8192
#define THREADS  512
#define NWARPS   (THREADS / 32)       // 16
#define PPT      (NPC / THREADS)      // 16
#define GROUPS   (PPT / 4)            // 4

typedef unsigned long long u64;

// 32-byte slot: key @0 (16-aligned), xy packed @8, z @16.
struct __align__(16) Slot { u64 key; u64 xy; float z; float pad[3]; };

struct __align__(16) Smem {
    float x[NPC];                // negated coords
    float y[NPC];
    float z[NPC];
    u64   wkey[NWARPS];          // per-warp packed (valBits<<32)|~localIdx
    Slot  slots[2][CLUSTER];     // parity-double-buffered cluster exchange
    u64   mbar;
};

__device__ __forceinline__ uint32_t smem_u32(const void* p) {
    return (uint32_t)__cvta_generic_to_shared(p);
}
__device__ __forceinline__ u64 pk2(float lo, float hi) {
    u64 r; asm("mov.b64 %0, {%1, %2};" : "=l"(r) : "f"(lo), "f"(hi)); return r;
}
__device__ __forceinline__ void upk2(float& lo, float& hi, u64 v) {
    asm("mov.b64 {%0, %1}, %2;" : "=f"(lo), "=f"(hi) : "l"(v));
}
__device__ __forceinline__ u64 add2(u64 a, u64 b) {
    u64 r; asm("add.rn.f32x2 %0, %1, %2;" : "=l"(r) : "l"(a), "l"(b)); return r;
}
__device__ __forceinline__ u64 mul2(u64 a, u64 b) {
    u64 r; asm("mul.rn.f32x2 %0, %1, %2;" : "=l"(r) : "l"(a), "l"(b)); return r;
}
__device__ __forceinline__ unsigned redux_max(unsigned v) {
    unsigned r; asm("redux.sync.max.u32 %0, %1, 0xffffffff;" : "=r"(r) : "r"(v)); return r;
}
__device__ __forceinline__ unsigned redux_min(unsigned v) {
    unsigned r; asm("redux.sync.min.u32 %0, %1, 0xffffffff;" : "=r"(r) : "r"(v)); return r;
}

__global__ void __launch_bounds__(THREADS, 2)
fps_kernel(const float* __restrict__ pc, float* __restrict__ out)
{
    extern __shared__ char smraw[];
    Smem& s = *reinterpret_cast<Smem*>(smraw);

    const int tid  = threadIdx.x;
    const int lane = tid & 31;
    const int warp = tid >> 5;
    const int rank = blockIdx.x & (CLUSTER - 1);
    const int b    = blockIdx.x >> 3;

    const float* __restrict__ base = pc + (size_t)b * NPTS * 3;

    // ---- prologue: stage NEGATED coords as SoA ----
    for (int i = tid; i < NPC; i += THREADS) {
        int gi = rank * NPC + i;
        s.x[i] = -base[gi * 3 + 0];
        s.y[i] = -base[gi * 3 + 1];
        s.z[i] = -base[gi * 3 + 2];
    }
    if (tid == 0) {
        asm volatile("mbarrier.init.shared.b64 [%0], %1;"
                     :: "r"(smem_u32(&s.mbar)), "r"(CLUSTER) : "memory");
    }

    float closest[PPT];
    #pragma unroll
    for (int i = 0; i < PPT; i++) closest[i] = __int_as_float(0x7f800000);

    float sx = base[0], sy = base[1], sz = base[2];   // initial selection: point 0

    __syncthreads();
    asm volatile("barrier.cluster.arrive.aligned;" ::: "memory");
    asm volatile("barrier.cluster.wait.aligned;"   ::: "memory");

    const uint32_t mb_addr = smem_u32(&s.mbar);

    for (int it = 0; it < NSAMP; ++it) {
        const int p = it & 1;

        u64 sxx = pk2(sx, sx), syy = pk2(sy, sy), szz = pk2(sz, sz);

        // ---- distance update + running min; value-only max (packed f32x2) ----
        float vmax = 0.0f;
        #pragma unroll
        for (int g = 0; g < GROUPS; ++g) {
            const int bi = g * (THREADS * 4) + tid * 4;
            ulonglong2 X = *reinterpret_cast<const ulonglong2*>(&s.x[bi]);
            ulonglong2 Y = *reinterpret_cast<const ulonglong2*>(&s.y[bi]);
            ulonglong2 Z = *reinterpret_cast<const ulonglong2*>(&s.z[bi]);
            {   // points 0,1 : d = (s + (-x))^2 + (s + (-y))^2 + (s + (-z))^2
                u64 dx = add2(sxx, X.x);
                u64 dy = add2(syy, Y.x);
                u64 dz = add2(szz, Z.x);
                u64 d  = add2(add2(mul2(dx, dx), mul2(dy, dy)), mul2(dz, dz));
                float d0, d1; upk2(d0, d1, d);
                float c0 = fminf(closest[g*4+0], d0); closest[g*4+0] = c0;
                float c1 = fminf(closest[g*4+1], d1); closest[g*4+1] = c1;
                vmax = fmaxf(vmax, c0); vmax = fmaxf(vmax, c1);
            }
            {   // points 2,3
                u64 dx = add2(sxx, X.y);
                u64 dy = add2(syy, Y.y);
                u64 dz = add2(szz, Z.y);
                u64 d  = add2(add2(mul2(dx, dx), mul2(dy, dy)), mul2(dz, dz));
                float d0, d1; upk2(d0, d1, d);
                float c0 = fminf(closest[g*4+2], d0); closest[g*4+2] = c0;
                float c1 = fminf(closest[g*4+3], d1); closest[g*4+3] = c1;
                vmax = fmaxf(vmax, c0); vmax = fmaxf(vmax, c1);
            }
        }

        // ---- warp reduce: redux max on float bits (all >= 0) ----
        const unsigned wmax = redux_max(__float_as_uint(vmax));

        // exact first index: parallel min over matching indices
        unsigned my = 0xffffffffu;
        #pragma unroll
        for (int g = 0; g < GROUPS; ++g) {
            #pragma unroll
            for (int j = 0; j < 4; ++j) {
                unsigned cand = (unsigned)(g * (THREADS * 4) + tid * 4 + j);
                if (__float_as_uint(closest[g*4+j]) == wmax)
                    my = (cand < my) ? cand : my;
            }
        }
        const unsigned wmin = redux_min(my);
        if (lane == 0)
            s.wkey[warp] = ((u64)wmax << 32) | (u64)(unsigned)(~wmin);
        __syncthreads();

        // ---- CTA reduce (warp 0, split-u32 redux) + push to all 8 peers ----
        if (warp == 0) {
            u64 wk = (lane < NWARPS) ? s.wkey[lane] : 0ull;
            unsigned vhi = (unsigned)(wk >> 32);
            unsigned vlo = (unsigned)wk;                       // ~localIdx
            unsigned Vmax = redux_max(vhi);
            unsigned nli  = redux_max((vhi == Vmax) ? vlo : 0u);  // max ~idx = min idx
            if (lane < CLUSTER) {
                unsigned li   = ~nli;
                unsigned gidx = (unsigned)rank * NPC + li;
                u64 ckey = ((u64)Vmax << 32) | (u64)(unsigned)(~gidx);
                float cx = -s.x[li], cy = -s.y[li], cz = -s.z[li];   // un-negate
                u64 xy = pk2(cx, cy);
                uint32_t sl = smem_u32(&s.slots[p][rank]);
                uint32_t rs, rb;
                asm volatile("mapa.shared::cluster.u32 %0, %1, %2;" : "=r"(rs) : "r"(sl),      "r"(lane));
                asm volatile("mapa.shared::cluster.u32 %0, %1, %2;" : "=r"(rb) : "r"(mb_addr), "r"(lane));
                asm volatile("st.shared::cluster.v2.b64 [%0], {%1, %2};"
                             :: "r"(rs), "l"(ckey), "l"(xy) : "memory");
                asm volatile("st.shared::cluster.f32 [%0+16], %1;" :: "r"(rs), "f"(cz) : "memory");
                asm volatile("mbarrier.arrive.release.cluster.shared::cluster.b64 _, [%0];"
                             :: "r"(rb) : "memory");
            }
        }

        // ---- wait for all 8 publishes ----
        asm volatile(
            "{\n\t.reg .pred P;\n"
            "W%=:\n\t"
            "mbarrier.try_wait.parity.acquire.cluster.shared::cta.b64 P, [%0], %1, 0x989680;\n\t"
            "@P bra.uni D%=;\n\t"
            "bra.uni W%=;\n"
            "D%=:\n\t}"
            :: "r"(mb_addr), "r"(p) : "memory");

        // ---- scan 8 local slots; winner coords are local ----
        const Slot* sl = s.slots[p];
        u64 bk = sl[0].key;
        int br = 0;
        #pragma unroll
        for (int r = 1; r < CLUSTER; ++r) {
            u64 kr = sl[r].key;
            if (kr > bk) { bk = kr; br = r; }
        }
        float nsx, nsy;
        upk2(nsx, nsy, sl[br].xy);
        float nsz = sl[br].z;

        if (rank == 0 && tid == 0) {
            float* o = out + ((size_t)b * NSAMP + it) * 3;
            o[0] = nsx; o[1] = nsy; o[2] = nsz;
        }
        sx = nsx; sy = nsy; sz = nsz;
    }
}

extern "C" void kernel_launch(void* const* d_in, const int* in_sizes, int n_in,
                              void* d_out, int out_size)
{
    (void)in_sizes; (void)n_in; (void)out_size;
    const float* pc  = (const float*)d_in[0];
    float*       out = (float*)d_out;

    static bool attr_set = false;
    if (!attr_set) {
        cudaFuncSetAttribute(fps_kernel,
                             cudaFuncAttributeMaxDynamicSharedMemorySize,
                             (int)sizeof(Smem));
        attr_set = true;
    }

    cudaLaunchConfig_t cfg = {};
    cfg.gridDim = dim3(NBATCH * CLUSTER, 1, 1);
    cfg.blockDim = dim3(THREADS, 1, 1);
    cfg.dynamicSmemBytes = sizeof(Smem);
    cfg.stream = 0;
    cudaLaunchAttribute attrs[1];
    attrs[0].id = cudaLaunchAttributeClusterDimension;
    attrs[0].val.clusterDim = {CLUSTER, 1, 1};
    cfg.attrs = attrs;
    cfg.numAttrs = 1;
    cudaLaunchKernelEx(&cfg, fps_kernel, pc, out);
}